// round 15
// baseline (speedup 1.0000x reference)
#include <cuda_runtime.h>
#include <cuda_fp16.h>

#define BB 8
#define CC 64
#define HH 64
#define WW 64
#define NROI 4096
#define NPER 512   // rois per batch-outer index
#define CLAMPB 50  // 64 - 14: window base clamp so base+13 <= 63

// NHWC fp16 scratch copy of the feature map (4 MB), 16B-aligned.
__device__ __align__(16) __half g_featH[BB * HH * WW * CC];

__device__ __forceinline__ unsigned h2_bits(__half2 h) {
    return *reinterpret_cast<unsigned*>(&h);
}
__device__ __forceinline__ __half2 bits_h2(unsigned u) {
    return *reinterpret_cast<__half2*>(&u);
}

// Antiderivative of the bilinear tent kernel max(0, 1-|t|), clipped.
__device__ __forceinline__ float tentI(float t) {
    t = fminf(1.0f, fmaxf(-1.0f, t));
    float a = t + 1.0f;
    float b = 1.0f - t;
    return (t < 0.0f) ? 0.5f * a * a : 1.0f - 0.5f * b * b;
}

// NCHW fp32 -> NHWC fp16 transpose, one 64(c)x64(x) tile per (b,y).
// float4 loads along x; uint4 (8 half) stores along c. 512 blocks x 256 threads.
__global__ __launch_bounds__(256) void transpose_nchw_nhwc(const float* __restrict__ feat) {
    __shared__ float tile[64][65];   // tile[x][c]
    int by = blockIdx.x;             // b*HH + y
    int b  = by >> 6;
    int y  = by & 63;
    int t  = threadIdx.x;

    int cRow = t >> 4;               // 0..15
    int x4   = (t & 15) << 2;        // 0,4,...,60
#pragma unroll
    for (int k = 0; k < 4; ++k) {
        int c = cRow + (k << 4);
        float4 v = *(const float4*)(feat + (((b * CC + c) * HH + y) * WW) + x4);
        tile[x4 + 0][c] = v.x;
        tile[x4 + 1][c] = v.y;
        tile[x4 + 2][c] = v.z;
        tile[x4 + 3][c] = v.w;
    }
    __syncthreads();

    int xr = t >> 3;                 // 0..31
    int cg = (t & 7) << 3;           // 0,8,...,56
#pragma unroll
    for (int k = 0; k < 2; ++k) {
        int x = xr + (k << 5);
        __half2 h0 = __floats2half2_rn(tile[x][cg + 0], tile[x][cg + 1]);
        __half2 h1 = __floats2half2_rn(tile[x][cg + 2], tile[x][cg + 3]);
        __half2 h2 = __floats2half2_rn(tile[x][cg + 4], tile[x][cg + 5]);
        __half2 h3 = __floats2half2_rn(tile[x][cg + 6], tile[x][cg + 7]);
        uint4 o;
        o.x = h2_bits(h0);  o.y = h2_bits(h1);
        o.z = h2_bits(h2);  o.w = h2_bits(h3);
        *(uint4*)(g_featH + ((size_t)(by * WW + x) * CC) + cg) = o;
    }
}

// 4 warps (128 lanes) per roi: 8 channel-lanes (uint4 = 8 fp16) x 16 y-phases,
// 1 row per thread (R13 structure, proven numerics). fp16 x-accumulation split
// into even/odd tap chains (8 HFMA2 chains, half the dependency depth; merged
// pairwise with __hadd2). Row result -> fp32, wy-scaled, reduced in fp32.
// 256-thread block = 2 rois. Grid = NROI/2 = 2048 blocks.
__global__ __launch_bounds__(256, 4) void proi_kernel(const float* __restrict__ rois,
                                                      float* __restrict__ out) {
    __shared__ __half2 wxh[2][16];      // (w, w) duplicated, fp16
    __shared__ float   wys[2][16];
    __shared__ float   inva[2];
    __shared__ float   partial[2][4][64];

    int tid   = threadIdx.x;
    int lane  = tid & 31;
    int warp  = tid >> 5;
    int roiIB = warp >> 2;              // roi within block: 0..1
    int wIR   = warp & 3;               // warp within roi: 0..3
    int li    = lane & 7;               // channel-group lane (c = 8*li..8*li+7)
    int pgrp  = lane >> 3;              // 0..3
    int phase = (wIR << 2) + pgrp;      // y-row 0..15 (14,15 always idle)

    int r = (blockIdx.x << 1) + roiIB;
    // output row r <-> roi storage (n*B + b_out), r = b_out*512 + n
    int b_out = r >> 9;
    int n     = r & (NPER - 1);
    const float* rp = rois + (n * BB + b_out) * 5;

    int   bidx = (int)__ldg(rp + 0);
    float x1   = __ldg(rp + 1);
    float y1   = __ldg(rp + 2);
    float x2   = __ldg(rp + 3);
    float y2   = __ldg(rp + 4);

    // Clamped 14-wide windows: tent weights outside the true box are exactly 0,
    // and base+13 <= 63 keeps guarded accesses in-bounds.
    int ix0 = min((int)floorf(x1), CLAMPB);   // x1 >= 0
    int iy0 = min((int)floorf(y1), CLAMPB);
    int ix1 = min(WW - 1, (int)ceilf(x2));
    int iy1 = min(HH - 1, (int)ceilf(y2));
    int nxW = ix1 - ix0 + 1;            // 5..14, uniform per roi
    int nyW = iy1 - iy0 + 1;            // 5..14, uniform per roi

    // One warp per roi computes the weights: lanes 0-15 -> wx, 16-31 -> wy.
    if (wIR == 0) {
        int  hw    = lane >> 4;
        int  wl    = lane & 15;
        float lo   = (hw == 0) ? x1 : y1;
        float hi   = (hw == 0) ? x2 : y2;
        int   base = (hw == 0) ? ix0 : iy0;
        float fi   = (float)(base + wl);
        float w    = tentI(hi - fi) - tentI(lo - fi);
        if (hw == 0) wxh[roiIB][wl] = __float2half2_rn(w);
        else         wys[roiIB][wl] = w;
        if (lane == 0)
            inva[roiIB] = 1.0f / ((x2 - x1) * (y2 - y1));
    }
    __syncthreads();

    float acc[8];
#pragma unroll
    for (int c = 0; c < 8; ++c) acc[c] = 0.0f;

    if (phase < nyW) {
        float wy = wys[roiIB][phase];
        const uint4* p = (const uint4*)(g_featH
            + ((size_t)((bidx * HH + iy0 + phase) * WW + ix0) * CC) + (li << 3));
        __half2 z = __float2half2_rn(0.0f);
        __half2 e0 = z, e1 = z, e2 = z, e3 = z;    // even taps
        __half2 o0 = z, o1 = z, o2 = z, o3 = z;    // odd taps
#pragma unroll
        for (int ii = 0; ii < 14; ii += 2) {
            if (ii < nxW) {             // warp-uniform predicate
                uint4 v = p[ii << 3];
                __half2 wp = wxh[roiIB][ii];
                e0 = __hfma2(wp, bits_h2(v.x), e0);
                e1 = __hfma2(wp, bits_h2(v.y), e1);
                e2 = __hfma2(wp, bits_h2(v.z), e2);
                e3 = __hfma2(wp, bits_h2(v.w), e3);
            }
            if (ii + 1 < nxW) {         // warp-uniform predicate
                uint4 v = p[(ii + 1) << 3];
                __half2 wp = wxh[roiIB][ii + 1];
                o0 = __hfma2(wp, bits_h2(v.x), o0);
                o1 = __hfma2(wp, bits_h2(v.y), o1);
                o2 = __hfma2(wp, bits_h2(v.z), o2);
                o3 = __hfma2(wp, bits_h2(v.w), o3);
            }
        }
        float2 f0 = __half22float2(__hadd2(e0, o0));
        float2 f1 = __half22float2(__hadd2(e1, o1));
        float2 f2 = __half22float2(__hadd2(e2, o2));
        float2 f3 = __half22float2(__hadd2(e3, o3));
        acc[0] = wy * f0.x;  acc[1] = wy * f0.y;
        acc[2] = wy * f1.x;  acc[3] = wy * f1.y;
        acc[4] = wy * f2.x;  acc[5] = wy * f2.y;
        acc[6] = wy * f3.x;  acc[7] = wy * f3.y;
    }

    // Reduce over the 4 phase-groups within the warp.
#pragma unroll
    for (int c = 0; c < 8; ++c) {
        acc[c] += __shfl_xor_sync(0xFFFFFFFFu, acc[c], 8, 32);
        acc[c] += __shfl_xor_sync(0xFFFFFFFFu, acc[c], 16, 32);
    }

    if (lane < 8) {
        float* dst = &partial[roiIB][wIR][lane << 3];
#pragma unroll
        for (int c = 0; c < 8; ++c) dst[c] = acc[c];
    }
    __syncthreads();

    // Final combine across the 4 warps of each roi; 128 threads write 2 rois.
    if (tid < 128) {
        int rid = tid >> 6;
        int c   = tid & 63;
        float s = partial[rid][0][c] + partial[rid][1][c]
                + partial[rid][2][c] + partial[rid][3][c];
        int rr = (blockIdx.x << 1) + rid;
        out[(rr << 6) + c] = s * inva[rid];
    }
}

extern "C" void kernel_launch(void* const* d_in, const int* in_sizes, int n_in,
                              void* d_out, int out_size) {
    const float* feature = (const float*)d_in[0];
    const float* rois    = (const float*)d_in[1];
    float* out           = (float*)d_out;

    transpose_nchw_nhwc<<<BB * HH, 256>>>(feature);
    proi_kernel<<<NROI / 2, 256>>>(rois, out);
}

// round 16
// speedup vs baseline: 1.1775x; 1.1775x over previous
#include <cuda_runtime.h>
#include <cuda_fp16.h>

#define BB 8
#define CC 64
#define HH 64
#define WW 64
#define NROI 4096
#define NPER 512   // rois per batch-outer index
#define CLAMPB 50  // 64 - 14: window base clamp so base+13 <= 63

// NHWC fp16 scratch copy of the feature map (4 MB), 16B-aligned.
__device__ __align__(16) __half g_featH[BB * HH * WW * CC];

__device__ __forceinline__ unsigned h2_bits(__half2 h) {
    return *reinterpret_cast<unsigned*>(&h);
}
__device__ __forceinline__ __half2 bits_h2(unsigned u) {
    return *reinterpret_cast<__half2*>(&u);
}

// Antiderivative of the bilinear tent kernel max(0, 1-|t|), clipped.
__device__ __forceinline__ float tentI(float t) {
    t = fminf(1.0f, fmaxf(-1.0f, t));
    float a = t + 1.0f;
    float b = 1.0f - t;
    return (t < 0.0f) ? 0.5f * a * a : 1.0f - 0.5f * b * b;
}

// NCHW fp32 -> NHWC fp16 transpose, one 64(c)x64(x) tile per (b,y).
// float4 loads along x; uint4 (8 half) stores along c. 512 blocks x 256 threads.
__global__ __launch_bounds__(256) void transpose_nchw_nhwc(const float* __restrict__ feat) {
    __shared__ float tile[64][65];   // tile[x][c]
    int by = blockIdx.x;             // b*HH + y
    int b  = by >> 6;
    int y  = by & 63;
    int t  = threadIdx.x;

    int cRow = t >> 4;               // 0..15
    int x4   = (t & 15) << 2;        // 0,4,...,60
#pragma unroll
    for (int k = 0; k < 4; ++k) {
        int c = cRow + (k << 4);
        float4 v = *(const float4*)(feat + (((b * CC + c) * HH + y) * WW) + x4);
        tile[x4 + 0][c] = v.x;
        tile[x4 + 1][c] = v.y;
        tile[x4 + 2][c] = v.z;
        tile[x4 + 3][c] = v.w;
    }
    __syncthreads();

    int xr = t >> 3;                 // 0..31
    int cg = (t & 7) << 3;           // 0,8,...,56
#pragma unroll
    for (int k = 0; k < 2; ++k) {
        int x = xr + (k << 5);
        __half2 h0 = __floats2half2_rn(tile[x][cg + 0], tile[x][cg + 1]);
        __half2 h1 = __floats2half2_rn(tile[x][cg + 2], tile[x][cg + 3]);
        __half2 h2 = __floats2half2_rn(tile[x][cg + 4], tile[x][cg + 5]);
        __half2 h3 = __floats2half2_rn(tile[x][cg + 6], tile[x][cg + 7]);
        uint4 o;
        o.x = h2_bits(h0);  o.y = h2_bits(h1);
        o.z = h2_bits(h2);  o.w = h2_bits(h3);
        *(uint4*)(g_featH + ((size_t)(by * WW + x) * CC) + cg) = o;
    }
}

// 2 warps (64 lanes) per roi: 8 channel-lanes (uint4 = 8 fp16) x 8 y-phases,
// 2 rows per thread (j = phase, phase+8) in two straight-line guarded blocks
// (R6 shape) with fp16 HFMA2 x-accumulation (R13 numerics). Up to 28 LDG.128
// in flight per thread. 256-thread block = 4 rois. Grid = NROI/4 = 1024.
__global__ __launch_bounds__(256, 4) void proi_kernel(const float* __restrict__ rois,
                                                      float* __restrict__ out) {
    __shared__ __half2 wxh[4][16];      // (w, w) duplicated, fp16
    __shared__ float   wys[4][16];
    __shared__ float   inva[4];
    __shared__ float   partial[4][2][64];

    int tid   = threadIdx.x;
    int lane  = tid & 31;
    int warp  = tid >> 5;
    int roiIB = warp >> 1;              // roi within block: 0..3
    int wIR   = warp & 1;               // warp within roi: 0..1
    int li    = lane & 7;               // channel-group lane (c = 8*li..8*li+7)
    int pgrp  = lane >> 3;              // 0..3
    int phase = (wIR << 2) + pgrp;      // y-row slot 0..7

    int r = (blockIdx.x << 2) + roiIB;
    // output row r <-> roi storage (n*B + b_out), r = b_out*512 + n
    int b_out = r >> 9;
    int n     = r & (NPER - 1);
    const float* rp = rois + (n * BB + b_out) * 5;

    int   bidx = (int)__ldg(rp + 0);
    float x1   = __ldg(rp + 1);
    float y1   = __ldg(rp + 2);
    float x2   = __ldg(rp + 3);
    float y2   = __ldg(rp + 4);

    // Clamped 14-wide windows: tent weights outside the true box are exactly 0,
    // and base+13 <= 63 keeps guarded accesses in-bounds.
    int ix0 = min((int)floorf(x1), CLAMPB);   // x1 >= 0
    int iy0 = min((int)floorf(y1), CLAMPB);
    int ix1 = min(WW - 1, (int)ceilf(x2));
    int iy1 = min(HH - 1, (int)ceilf(y2));
    int nxW = ix1 - ix0 + 1;            // 5..14, uniform per roi
    int nyW = iy1 - iy0 + 1;            // 5..14, uniform per roi

    // One warp per roi computes the weights: lanes 0-15 -> wx, 16-31 -> wy.
    if (wIR == 0) {
        int  hw    = lane >> 4;
        int  wl    = lane & 15;
        float lo   = (hw == 0) ? x1 : y1;
        float hi   = (hw == 0) ? x2 : y2;
        int   base = (hw == 0) ? ix0 : iy0;
        float fi   = (float)(base + wl);
        float w    = tentI(hi - fi) - tentI(lo - fi);
        if (hw == 0) wxh[roiIB][wl] = __float2half2_rn(w);
        else         wys[roiIB][wl] = w;
        if (lane == 0)
            inva[roiIB] = 1.0f / ((x2 - x1) * (y2 - y1));
    }
    __syncthreads();

    const __half* fb = g_featH
        + ((size_t)((bidx * HH + iy0) * WW + ix0) * CC) + (li << 3);

    float acc[8];
#pragma unroll
    for (int c = 0; c < 8; ++c) acc[c] = 0.0f;

    // Row 1: j = phase (active when phase < nyW; nyW >= 5 so pgrp-divergence
    // only in warp covering phases 4..7).
    if (phase < nyW) {
        float wy = wys[roiIB][phase];
        const uint4* p = (const uint4*)(fb + (size_t)phase * (WW * CC));
        __half2 z = __float2half2_rn(0.0f);
        __half2 r0 = z, r1 = z, r2 = z, r3 = z;
#pragma unroll
        for (int ii = 0; ii < 14; ++ii) {
            if (ii < nxW) {             // warp-uniform predicate
                uint4 v = p[ii << 3];   // tap stride = 128 B = 8 uint4
                __half2 wp = wxh[roiIB][ii];
                r0 = __hfma2(wp, bits_h2(v.x), r0);
                r1 = __hfma2(wp, bits_h2(v.y), r1);
                r2 = __hfma2(wp, bits_h2(v.z), r2);
                r3 = __hfma2(wp, bits_h2(v.w), r3);
            }
        }
        float2 f0 = __half22float2(r0);
        float2 f1 = __half22float2(r1);
        float2 f2 = __half22float2(r2);
        float2 f3 = __half22float2(r3);
        acc[0] = wy * f0.x;  acc[1] = wy * f0.y;
        acc[2] = wy * f1.x;  acc[3] = wy * f1.y;
        acc[4] = wy * f2.x;  acc[5] = wy * f2.y;
        acc[6] = wy * f3.x;  acc[7] = wy * f3.y;
    }

    // Row 2: j = phase + 8 (guard also bounds wys index: phase+8 <= 15).
    if (phase + 8 < nyW) {
        float wy = wys[roiIB][phase + 8];
        const uint4* p = (const uint4*)(fb + (size_t)(phase + 8) * (WW * CC));
        __half2 z = __float2half2_rn(0.0f);
        __half2 r0 = z, r1 = z, r2 = z, r3 = z;
#pragma unroll
        for (int ii = 0; ii < 14; ++ii) {
            if (ii < nxW) {             // warp-uniform predicate
                uint4 v = p[ii << 3];
                __half2 wp = wxh[roiIB][ii];
                r0 = __hfma2(wp, bits_h2(v.x), r0);
                r1 = __hfma2(wp, bits_h2(v.y), r1);
                r2 = __hfma2(wp, bits_h2(v.z), r2);
                r3 = __hfma2(wp, bits_h2(v.w), r3);
            }
        }
        float2 f0 = __half22float2(r0);
        float2 f1 = __half22float2(r1);
        float2 f2 = __half22float2(r2);
        float2 f3 = __half22float2(r3);
        acc[0] = fmaf(wy, f0.x, acc[0]);  acc[1] = fmaf(wy, f0.y, acc[1]);
        acc[2] = fmaf(wy, f1.x, acc[2]);  acc[3] = fmaf(wy, f1.y, acc[3]);
        acc[4] = fmaf(wy, f2.x, acc[4]);  acc[5] = fmaf(wy, f2.y, acc[5]);
        acc[6] = fmaf(wy, f3.x, acc[6]);  acc[7] = fmaf(wy, f3.y, acc[7]);
    }

    // Reduce over the 4 phase-groups within the warp.
#pragma unroll
    for (int c = 0; c < 8; ++c) {
        acc[c] += __shfl_xor_sync(0xFFFFFFFFu, acc[c], 8, 32);
        acc[c] += __shfl_xor_sync(0xFFFFFFFFu, acc[c], 16, 32);
    }

    if (lane < 8) {
        float* dst = &partial[roiIB][wIR][lane << 3];
#pragma unroll
        for (int c = 0; c < 8; ++c) dst[c] = acc[c];
    }
    __syncthreads();

    // Final combine across the 2 warps of each roi; 256 threads write 4 rois.
    {
        int rid = tid >> 6;             // 0..3
        int c   = tid & 63;
        float s = partial[rid][0][c] + partial[rid][1][c];
        int rr = (blockIdx.x << 2) + rid;
        out[(rr << 6) + c] = s * inva[rid];
    }
}

extern "C" void kernel_launch(void* const* d_in, const int* in_sizes, int n_in,
                              void* d_out, int out_size) {
    const float* feature = (const float*)d_in[0];
    const float* rois    = (const float*)d_in[1];
    float* out           = (float*)d_out;

    transpose_nchw_nhwc<<<BB * HH, 256>>>(feature);
    proi_kernel<<<NROI / 4, 256>>>(rois, out);
}